// round 3
// baseline (speedup 1.0000x reference)
#include <cuda_runtime.h>

// SyntacticGCN fused kernel for GB300 (sm_103a) — R3: M-split x2, 32 warps/SM, dense coalescing
// B=16, S=128, M=128, D=256, H=256

#define BB 16
#define SS 128
#define MM 128
#define DD 256
#define HH 256
#define NROWS (BB * SS)   // 2048
#define RPC 8             // rows per CTA
#define NTHREADS 512      // 16 warps: warp w -> row (w>>1), m-half (w&1)

__global__ __launch_bounds__(NTHREADS, 2)
void gcn_fused_kernel(const float* __restrict__ src,
                      const float* __restrict__ ngh,
                      const float* __restrict__ Wm,   // [2D, H] row-major
                      const float* __restrict__ bm,   // [H]
                      float* __restrict__ out)        // [NROWS, H]
{
    __shared__ float hid[RPC][2 * DD];     // 16 KB: h=0 partials, then combined hidden
    __shared__ float parts[RPC][2 * DD];   // 16 KB: h=1 partials; reused as GEMM partial buffer
    __shared__ int   cnts[2 * RPC];

    const int tid  = threadIdx.x;
    const int warp = tid >> 5;
    const int lane = tid & 31;
    const int r    = warp >> 1;     // row within CTA
    const int h    = warp & 1;      // m-half
    const int row0 = blockIdx.x * RPC;

    // ---------------- Phase 1: (row, m-half) per warp, dense coalesced loads ----------------
    {
        const int row = row0 + r;
        // lane owns cols [4*lane, 4*lane+4) and [128+4*lane, 128+4*lane+4)
        const float4* sp = (const float4*)(src + (size_t)row * MM * DD);
        const float4* np = (const float4*)(ngh + (size_t)row * MM * DD);

        float4 sa0 = make_float4(0.f, 0.f, 0.f, 0.f);
        float4 sa1 = make_float4(0.f, 0.f, 0.f, 0.f);
        float4 na0 = make_float4(0.f, 0.f, 0.f, 0.f);
        float4 na1 = make_float4(0.f, 0.f, 0.f, 0.f);
        int cnt = 0;

        const int mbase = h * (MM / 2);
        #pragma unroll 2
        for (int i = 0; i < MM / 2; ++i) {
            const int moff = (mbase + i) * (DD / 4);
            // each LDG.128 below: 32 lanes x 16B contiguous = 4 full 128B lines
            float4 s0 = __ldg(sp + moff + lane);        // cols [0,128)
            float4 s1 = __ldg(sp + moff + 32 + lane);   // cols [128,256)
            float4 n0 = __ldg(np + moff + lane);
            float4 n1 = __ldg(np + moff + 32 + lane);

            sa0.x += s0.x; sa0.y += s0.y; sa0.z += s0.z; sa0.w += s0.w;
            sa1.x += s1.x; sa1.y += s1.y; sa1.z += s1.z; sa1.w += s1.w;
            na0.x += n0.x; na0.y += n0.y; na0.z += n0.z; na0.w += n0.w;
            na1.x += n1.x; na1.y += n1.y; na1.z += n1.z; na1.w += n1.w;

            bool nz = (n0.x != 0.f) | (n0.y != 0.f) | (n0.z != 0.f) | (n0.w != 0.f) |
                      (n1.x != 0.f) | (n1.y != 0.f) | (n1.z != 0.f) | (n1.w != 0.f);
            if (__any_sync(0xffffffffu, nz)) cnt++;
        }

        // stage partials: h=0 -> hid, h=1 -> parts (conflict-free float4 stores)
        float4* dst = (h == 0) ? (float4*)&hid[r][0] : (float4*)&parts[r][0];
        dst[lane]      = sa0;   // src cols [0,128)
        dst[32 + lane] = sa1;   // src cols [128,256)
        dst[64 + lane] = na0;   // neigh cols [0,128)
        dst[96 + lane] = na1;   // neigh cols [128,256)
        if (lane == 0) cnts[warp] = cnt;
    }
    __syncthreads();

    // ---------------- Combine halves + scale neigh mean ----------------
    #pragma unroll
    for (int i = 0; i < (RPC * 2 * DD) / NTHREADS; ++i) {   // 8 iters
        const int idx = tid + i * NTHREADS;                 // 0..4095
        const int rr  = idx >> 9;                           // row
        const int k   = idx & (2 * DD - 1);                 // hidden col
        float v = hid[rr][k] + parts[rr][k];
        if (k >= DD) {
            float c = (float)(cnts[2 * rr] + cnts[2 * rr + 1]);
            v *= 1.0f / fmaxf(c, 1.0f);
        }
        hid[rr][k] = v;
    }
    __syncthreads();

    // ---------------- Phase 2: GEMM (k split across thread halves) ----------------
    const int j  = tid & (HH - 1);   // output column
    const int kp = tid >> 8;         // k-part: 0 -> k[0,256), 1 -> k[256,512)

    float acc[RPC];
    #pragma unroll
    for (int r2 = 0; r2 < RPC; ++r2) acc[r2] = 0.f;

    const int k0 = kp * DD;
    #pragma unroll 2
    for (int kq = 0; kq < DD / 4; ++kq) {
        const int k = k0 + kq * 4;
        float w0 = __ldg(Wm + (size_t)(k + 0) * HH + j);
        float w1 = __ldg(Wm + (size_t)(k + 1) * HH + j);
        float w2 = __ldg(Wm + (size_t)(k + 2) * HH + j);
        float w3 = __ldg(Wm + (size_t)(k + 3) * HH + j);
        #pragma unroll
        for (int r2 = 0; r2 < RPC; ++r2) {
            float4 hv = *(const float4*)&hid[r2][k];   // smem broadcast, 128-bit
            acc[r2] = fmaf(hv.x, w0, acc[r2]);
            acc[r2] = fmaf(hv.y, w1, acc[r2]);
            acc[r2] = fmaf(hv.z, w2, acc[r2]);
            acc[r2] = fmaf(hv.w, w3, acc[r2]);
        }
    }

    __syncthreads();   // parts free for reuse (all combine reads done at earlier sync)
    float* gacc = &parts[0][0];   // [RPC][HH] partial accumulators
    if (kp == 1) {
        #pragma unroll
        for (int r2 = 0; r2 < RPC; ++r2) gacc[r2 * HH + j] = acc[r2];
    }
    __syncthreads();

    if (kp == 0) {
        const float bj = __ldg(bm + j);
        #pragma unroll
        for (int r2 = 0; r2 < RPC; ++r2) {
            float v = acc[r2] + gacc[r2 * HH + j] + bj;
            out[(size_t)(row0 + r2) * HH + j] = (v > 0.f) ? v : 0.01f * v;
        }
    }
}

extern "C" void kernel_launch(void* const* d_in, const int* in_sizes, int n_in,
                              void* d_out, int out_size)
{
    const float* src = (const float*)d_in[0];   // [B,S,M,D]
    const float* ngh = (const float*)d_in[1];   // [B,S,M,D]
    const float* Wm  = (const float*)d_in[2];   // [2D,H]
    const float* bm  = (const float*)d_in[3];   // [H]
    float* out = (float*)d_out;                 // [B*S, H]

    gcn_fused_kernel<<<NROWS / RPC, NTHREADS>>>(src, ngh, Wm, bm, out);
}

// round 4
// speedup vs baseline: 1.1264x; 1.1264x over previous
#include <cuda_runtime.h>
#include <cstdint>

// SyntacticGCN fused kernel for GB300 (sm_103a)
// R4: cp.async.bulk streaming pipeline (producer warp) + smem consumers
// B=16, S=128, M=128, D=256, H=256

#define BB 16
#define SS 128
#define MM 128
#define DD 256
#define HH 256
#define NROWS (BB * SS)     // 2048
#define RPC 8               // rows per CTA
#define NCONS 256           // consumer threads
#define NTHREADS 288        // + 1 producer warp
#define NSTAGES 4
#define CH_M 8                          // m-rows per chunk
#define CH_BYTES (CH_M * DD * 4)        // 8192 per matrix
#define STAGE_BYTES (2 * CH_BYTES)      // 16384 (src + neigh)
#define CHUNKS_PER_ROW (MM / CH_M)      // 16

// dynamic smem layout (bytes)
#define SBUF_OFF   0
#define SBUF_SZ    (NSTAGES * STAGE_BYTES)        // 65536
#define HID_OFF    (SBUF_OFF + SBUF_SZ)           // 65536
#define HID_SZ     (RPC * 2 * DD * 4)             // 16384
#define VMASK_OFF  (HID_OFF + HID_SZ)             // 81920
#define VMASK_SZ   (RPC * 4 * 4)                  // 128
#define MBAR_OFF   (VMASK_OFF + VMASK_SZ)         // 82048
#define MBAR_SZ    (NSTAGES * 16)                 // 64
#define SMEM_TOTAL (MBAR_OFF + MBAR_SZ)           // 82112

__device__ __forceinline__ uint32_t smem_u32(const void* p) {
    uint32_t a;
    asm("{ .reg .u64 t; cvta.to.shared.u64 t, %1; cvt.u32.u64 %0, t; }" : "=r"(a) : "l"(p));
    return a;
}

#define MBAR_INIT(addr, cnt) \
    asm volatile("mbarrier.init.shared.b64 [%0], %1;" :: "r"(addr), "r"(cnt) : "memory")

#define MBAR_EXPECT_TX(addr, bytes) \
    asm volatile("mbarrier.arrive.expect_tx.shared.b64 _, [%0], %1;" :: "r"(addr), "r"(bytes) : "memory")

#define MBAR_ARRIVE(addr) \
    asm volatile("mbarrier.arrive.shared.b64 _, [%0];" :: "r"(addr) : "memory")

// acquire wait (consumers: generic smem loads follow)
#define MBAR_WAIT(addr, parity) do {                                              \
    uint32_t _m = (addr), _p = (parity), _d;                                      \
    asm volatile("{\n\t.reg .pred p;\n\t"                                         \
        "mbarrier.try_wait.parity.acquire.cta.shared::cta.b64 p, [%1], %2;\n\t"   \
        "selp.b32 %0, 1, 0, p;\n\t}"                                              \
        : "=r"(_d) : "r"(_m), "r"(_p) : "memory");                                \
    if (!_d) {                                                                    \
        asm volatile("{\n\t.reg .pred P1;\n\t"                                    \
            "W_%=:\n\t"                                                           \
            "mbarrier.try_wait.parity.acquire.cta.shared::cta.b64 P1, [%0], %1, 0x989680;\n\t" \
            "@P1 bra.uni D_%=;\n\t"                                               \
            "bra.uni W_%=;\n\t"                                                   \
            "D_%=:\n\t}" :: "r"(_m), "r"(_p) : "memory");                         \
    }                                                                             \
} while (0)

// relaxed wait (producer: post-wait writes are async-proxy TMA only)
#define MBAR_WAIT_RELAXED(addr, parity) do {                                      \
    uint32_t _m = (addr), _p = (parity), _d;                                      \
    asm volatile("{\n\t.reg .pred p;\n\t"                                         \
        "mbarrier.try_wait.parity.relaxed.cta.shared::cta.b64 p, [%1], %2, 0x989680;\n\t" \
        "selp.b32 %0, 1, 0, p;\n\t}"                                              \
        : "=r"(_d) : "r"(_m), "r"(_p) : "memory");                                \
    if (!_d) {                                                                    \
        asm volatile("{\n\t.reg .pred P1;\n\t"                                    \
            "W_%=:\n\t"                                                           \
            "mbarrier.try_wait.parity.relaxed.cta.shared::cta.b64 P1, [%0], %1, 0x989680;\n\t" \
            "@P1 bra.uni D_%=;\n\t"                                               \
            "bra.uni W_%=;\n\t"                                                   \
            "D_%=:\n\t}" :: "r"(_m), "r"(_p) : "memory");                         \
    }                                                                             \
} while (0)

#define BULK_G2S(dst_smem, src_gmem, bytes, mbar)                                 \
    asm volatile("cp.async.bulk.shared::cta.global.mbarrier::complete_tx::bytes " \
                 "[%0], [%1], %2, [%3];"                                          \
                 :: "r"(dst_smem), "l"(src_gmem), "r"(bytes), "r"(mbar) : "memory")

__global__ __launch_bounds__(NTHREADS, 2)
void gcn_fused_kernel(const float* __restrict__ src,
                      const float* __restrict__ ngh,
                      const float* __restrict__ Wm,   // [2D, H] row-major
                      const float* __restrict__ bm,   // [H]
                      float* __restrict__ out)        // [NROWS, H]
{
    extern __shared__ __align__(128) char dsm[];

    const int tid  = threadIdx.x;
    const int warp = tid >> 5;
    const int lane = tid & 31;
    const int row0 = blockIdx.x * RPC;

    const uint32_t sb = smem_u32(dsm);
    float*    hid   = (float*)(dsm + HID_OFF);        // [RPC][2*DD]
    uint32_t* vmask = (uint32_t*)(dsm + VMASK_OFF);   // [RPC][4] (128-bit per row)

    // ---- init ----
    if (tid == 0) {
        #pragma unroll
        for (int s = 0; s < NSTAGES; ++s) {
            MBAR_INIT(sb + MBAR_OFF + s * 16,     1);      // full: 1 expect_tx arrive
            MBAR_INIT(sb + MBAR_OFF + s * 16 + 8, 8);      // empty: 8 consumer warps
        }
    }
    if (tid < RPC * 4) vmask[tid] = 0u;
    __syncthreads();   // only CTA-wide barrier; before any mbarrier use

    if (warp == 8) {
        // ---------------- producer warp ----------------
        if (lane == 0) {
            int stage = 0, phase = 1;   // phase=1: first NSTAGES empty-waits pass
            for (int it = 0; it < RPC * CHUNKS_PER_ROW; ++it) {
                const int r = it >> 4, c = it & (CHUNKS_PER_ROW - 1);
                const uint32_t emptyb = sb + MBAR_OFF + stage * 16 + 8;
                const uint32_t fullb  = sb + MBAR_OFF + stage * 16;
                MBAR_WAIT_RELAXED(emptyb, phase);
                MBAR_EXPECT_TX(fullb, STAGE_BYTES);
                const size_t eoff = ((size_t)(row0 + r) * MM + (size_t)c * CH_M) * DD;
                BULK_G2S(sb + SBUF_OFF + stage * STAGE_BYTES,
                         (const void*)(src + eoff), CH_BYTES, fullb);
                BULK_G2S(sb + SBUF_OFF + stage * STAGE_BYTES + CH_BYTES,
                         (const void*)(ngh + eoff), CH_BYTES, fullb);
                if (++stage == NSTAGES) { stage = 0; phase ^= 1; }
            }
        }
        return;   // producer warp done
    }

    // ---------------- consumers: 256 threads, thread t owns column t ----------------
    {
        const int t = tid;
        int stage = 0, phase = 0;
        for (int r = 0; r < RPC; ++r) {
            float ssum = 0.f, nsum = 0.f;
            for (int c = 0; c < CHUNKS_PER_ROW; ++c) {
                const uint32_t fullb  = sb + MBAR_OFF + stage * 16;
                const uint32_t emptyb = sb + MBAR_OFF + stage * 16 + 8;
                MBAR_WAIT(fullb, phase);

                const float* ss = (const float*)(dsm + SBUF_OFF + stage * STAGE_BYTES);
                const float* nn = ss + CH_M * DD;
                uint32_t nzbits = 0;
                #pragma unroll
                for (int m = 0; m < CH_M; ++m) {
                    float s = ss[m * DD + t];
                    float n = nn[m * DD + t];
                    ssum += s;
                    nsum += n;
                    nzbits |= (n != 0.f) ? (1u << m) : 0u;
                }
                uint32_t wor = __reduce_or_sync(0xffffffffu, nzbits);
                if (lane == 0 && wor)
                    atomicOr(&vmask[r * 4 + (c >> 2)], wor << ((c & 3) * 8));

                __syncwarp();
                if (lane == 0) MBAR_ARRIVE(emptyb);
                if (++stage == NSTAGES) { stage = 0; phase ^= 1; }
            }
            // consumer-only barrier: all warps' atomicOrs for row r complete
            asm volatile("bar.sync 1, %0;" :: "n"(NCONS) : "memory");
            int cnt = __popc(vmask[r * 4 + 0]) + __popc(vmask[r * 4 + 1]) +
                      __popc(vmask[r * 4 + 2]) + __popc(vmask[r * 4 + 3]);
            float inv = 1.0f / fmaxf((float)cnt, 1.0f);
            hid[r * 2 * DD + t]      = ssum;
            hid[r * 2 * DD + DD + t] = nsum * inv;
        }
    }
    asm volatile("bar.sync 1, %0;" :: "n"(NCONS) : "memory");   // hid fully written

    // ---------------- GEMM + bias + leaky_relu (as R1) ----------------
    const int j = tid;
    float acc[RPC];
    const float bj = __ldg(bm + j);
    #pragma unroll
    for (int r = 0; r < RPC; ++r) acc[r] = bj;

    #pragma unroll 2
    for (int k = 0; k < 2 * DD; k += 4) {
        float w0 = __ldg(Wm + (size_t)(k + 0) * HH + j);
        float w1 = __ldg(Wm + (size_t)(k + 1) * HH + j);
        float w2 = __ldg(Wm + (size_t)(k + 2) * HH + j);
        float w3 = __ldg(Wm + (size_t)(k + 3) * HH + j);
        #pragma unroll
        for (int r = 0; r < RPC; ++r) {
            float4 h = *(const float4*)(hid + r * 2 * DD + k);   // smem broadcast
            acc[r] = fmaf(h.x, w0, acc[r]);
            acc[r] = fmaf(h.y, w1, acc[r]);
            acc[r] = fmaf(h.z, w2, acc[r]);
            acc[r] = fmaf(h.w, w3, acc[r]);
        }
    }

    #pragma unroll
    for (int r = 0; r < RPC; ++r) {
        float v = acc[r];
        out[(size_t)(row0 + r) * HH + j] = (v > 0.f) ? v : 0.01f * v;
    }
}

extern "C" void kernel_launch(void* const* d_in, const int* in_sizes, int n_in,
                              void* d_out, int out_size)
{
    const float* src = (const float*)d_in[0];   // [B,S,M,D]
    const float* ngh = (const float*)d_in[1];   // [B,S,M,D]
    const float* Wm  = (const float*)d_in[2];   // [2D,H]
    const float* bm  = (const float*)d_in[3];   // [H]
    float* out = (float*)d_out;                 // [B*S, H]

    cudaFuncSetAttribute(gcn_fused_kernel,
                         cudaFuncAttributeMaxDynamicSharedMemorySize, SMEM_TOTAL);
    gcn_fused_kernel<<<NROWS / RPC, NTHREADS, SMEM_TOTAL>>>(src, ngh, Wm, bm, out);
}